// round 11
// baseline (speedup 1.0000x reference)
#include <cuda_runtime.h>
#include <cstdint>

#define N_NODES 50000
#define E_EDGES 800000
#define DIM 128
#define NEG_INF_F __int_as_float(0xff800000)

#define SCAN_B 49          // 49 blocks * 1024 = 50176 >= N_NODES+1
#define SCAN_T 1024
#define HIST_PER_T 16      // 49*1024*16 = 802816 >= E_EDGES

// ---------------------------------------------------------------------------
// Static device scratch. Invariant: g_cnt, g_cur, g_blksum, g_done* are zero
// at entry of every kernel_launch call. Graph-replay deterministic.
// ---------------------------------------------------------------------------
__device__ float g_agg[(size_t)N_NODES * DIM];   // post-agg: fused GEMM1 input
__device__ float g_h[(size_t)N_NODES * DIM];
__device__ int   g_is64;
__device__ int   g_cnt[N_NODES];
__device__ int   g_row[N_NODES + 1];
__device__ int   g_cur[N_NODES];
__device__ int   g_blksum[SCAN_B];
__device__ int   g_done1;
__device__ int   g_done2;
__device__ int2  g_edge[E_EDGES];

// ---------------------------------------------------------------------------
// Kernel 0: fused histogram + exclusive scan (single launch, 49 blocks).
// ---------------------------------------------------------------------------
__global__ void __launch_bounds__(SCAN_T, 1)
histscan_kernel(const int* __restrict__ ei32) {
    __shared__ int sh[SCAN_T];
    __shared__ int pre[SCAN_B];
    __shared__ int offset;
    __shared__ int any_nonzero;
    __shared__ int bar_ok;

    int t = threadIdx.x;
    int b = blockIdx.x;

    if (t == 0) any_nonzero = 0;
    __syncthreads();
    if (t < 256) {
        int k = t * 3000;
        if (ei32[2 * k + 1] != 0) atomicOr(&any_nonzero, 1);
    }
    __syncthreads();
    int is64 = any_nonzero ? 0 : 1;
    if (b == 0 && t == 0) g_is64 = is64;

    const long long* e64 = (const long long*)ei32;
    #pragma unroll
    for (int i = 0; i < HIST_PER_T; ++i) {
        int e = b * SCAN_T + t + i * (SCAN_B * SCAN_T);
        if (e < E_EDGES) {
            int src, dst;
            if (is64) {
                src = (int)e64[e];
                dst = (int)e64[(size_t)E_EDGES + e];
            } else {
                src = ei32[e];
                dst = ei32[(size_t)E_EDGES + e];
            }
            if ((unsigned)src < N_NODES && (unsigned)dst < N_NODES)
                atomicAdd(&g_cnt[dst], 1);
        }
    }

    __threadfence();
    __syncthreads();
    if (t == 0) {
        atomicAdd(&g_done1, 1);
        while (((volatile int*)&g_done1)[0] < SCAN_B) { }
        bar_ok = 1;
    }
    __syncthreads();
    (void)bar_ok;
    __threadfence();

    int idx = b * SCAN_T + t;
    int c = (idx < N_NODES) ? g_cnt[idx] : 0;
    if (idx < N_NODES) g_cnt[idx] = 0;
    sh[t] = c;
    __syncthreads();
    #pragma unroll
    for (int off = 1; off < SCAN_T; off <<= 1) {
        int v = (t >= off) ? sh[t - off] : 0;
        __syncthreads();
        sh[t] += v;
        __syncthreads();
    }
    int ex = sh[t] - c;
    if (t == SCAN_T - 1)
        ((volatile int*)g_blksum)[b] = sh[t] + 1;

    if (t < SCAN_B) {
        int v;
        do { v = ((volatile int*)g_blksum)[t]; } while (v == 0);
        pre[t] = v - 1;
    }
    __syncthreads();
    if (t == 0) {
        int s = 0;
        for (int i = 0; i < b; ++i) s += pre[i];
        offset = s;
    }
    __syncthreads();

    if (idx <= N_NODES) g_row[idx] = ex + offset;
    if (idx < N_NODES)  g_cur[idx] = 0;

    if (t == 0) {
        int old = atomicAdd(&g_done2, 1);
        if (old == SCAN_B - 1) {
            for (int i = 0; i < SCAN_B; ++i) g_blksum[i] = 0;
            g_done1 = 0;
            g_done2 = 0;
        }
    }
}

// ---------------------------------------------------------------------------
// Kernel 1: bucket edges by dst
// ---------------------------------------------------------------------------
__global__ void fill_kernel(const int* __restrict__ ei32,
                            const float* __restrict__ ew) {
    int e = blockIdx.x * blockDim.x + threadIdx.x;
    if (e >= E_EDGES) return;
    int src, dst;
    if (g_is64) {
        const long long* e64 = (const long long*)ei32;
        src = (int)e64[e];
        dst = (int)e64[(size_t)E_EDGES + e];
    } else {
        src = ei32[e];
        dst = ei32[(size_t)E_EDGES + e];
    }
    if ((unsigned)src >= N_NODES || (unsigned)dst >= N_NODES) return;
    int pos = g_row[dst] + atomicAdd(&g_cur[dst], 1);
    g_edge[pos] = make_int2(src, __float_as_int(ew[e]));
}

// ---------------------------------------------------------------------------
// Kernel 2: aggregate + fuse. One warp per dst node. Writes the complete
// GEMM1 input: g_agg[n] = (1+eps)*x[n] + max_agg[n] (0 for isolated nodes).
// ---------------------------------------------------------------------------
__device__ __forceinline__ float4 max4w(float4 a, float4 v, float w) {
    a.x = fmaxf(a.x, v.x * w);
    a.y = fmaxf(a.y, v.y * w);
    a.z = fmaxf(a.z, v.z * w);
    a.w = fmaxf(a.w, v.w * w);
    return a;
}

__global__ void agg_kernel(const float* __restrict__ x,
                           const float* __restrict__ eps) {
    int warp = (blockIdx.x * blockDim.x + threadIdx.x) >> 5;
    if (warp >= N_NODES) return;
    int lane = threadIdx.x & 31;
    int beg = __ldg(&g_row[warp]);
    int end = __ldg(&g_row[warp + 1]);

    float4 acc = make_float4(NEG_INF_F, NEG_INF_F, NEG_INF_F, NEG_INF_F);
    int j = beg;
    for (; j + 8 <= end; j += 8) {
        int2 e[8];
        #pragma unroll
        for (int i = 0; i < 8; ++i) e[i] = __ldg(&g_edge[j + i]);
        float4 v[8];
        #pragma unroll
        for (int i = 0; i < 8; ++i)
            v[i] = __ldg(&((const float4*)(x + (size_t)e[i].x * DIM))[lane]);
        #pragma unroll
        for (int i = 0; i < 8; ++i)
            acc = max4w(acc, v[i], __int_as_float(e[i].y));
    }
    if (j + 4 <= end) {
        int2 e[4];
        #pragma unroll
        for (int i = 0; i < 4; ++i) e[i] = __ldg(&g_edge[j + i]);
        float4 v[4];
        #pragma unroll
        for (int i = 0; i < 4; ++i)
            v[i] = __ldg(&((const float4*)(x + (size_t)e[i].x * DIM))[lane]);
        #pragma unroll
        for (int i = 0; i < 4; ++i)
            acc = max4w(acc, v[i], __int_as_float(e[i].y));
        j += 4;
    }
    for (; j < end; ++j) {
        int2 ep = __ldg(&g_edge[j]);
        float4 v = __ldg(&((const float4*)(x + (size_t)ep.x * DIM))[lane]);
        acc = max4w(acc, v, __int_as_float(ep.y));
    }
    if (beg == end) acc = make_float4(0.f, 0.f, 0.f, 0.f);

    // Fuse: (1+eps)*x[warp] + acc
    float s = 1.0f + __ldg(eps);
    float4 xv = __ldg(&((const float4*)(x + (size_t)warp * DIM))[lane]);
    acc.x = fmaf(s, xv.x, acc.x);
    acc.y = fmaf(s, xv.y, acc.y);
    acc.z = fmaf(s, xv.z, acc.z);
    acc.w = fmaf(s, xv.w, acc.w);
    ((float4*)(g_agg + (size_t)warp * DIM))[lane] = acc;
}

// ---------------------------------------------------------------------------
// Packed fp32x2 helpers (sm_103a FFMA2 — PTX-only)
// ---------------------------------------------------------------------------
__device__ __forceinline__ unsigned long long pack2(float v) {
    unsigned long long r;
    asm("mov.b64 %0, {%1, %1};" : "=l"(r) : "f"(v));
    return r;
}
__device__ __forceinline__ void fma2(unsigned long long& d,
                                     unsigned long long a,
                                     unsigned long long b) {
    asm("fma.rn.f32x2 %0, %1, %2, %0;" : "+l"(d) : "l"(a), "l"(b));
}
__device__ __forceinline__ void unpack2(unsigned long long v, float& lo, float& hi) {
    asm("mov.b64 {%0, %1}, %2;" : "=f"(lo), "=f"(hi) : "l"(v));
}

// ---------------------------------------------------------------------------
// GEMM: OUT[m,o] = act( A[m,:] @ W[o,:]^T + Bias[o] )
// BM=128 x BN=128, 512 threads, __launch_bounds__(512,2) -> 2 CTA/SM,
// 32 warps/SM (occ 50%). Smem = W only (transposed, LDW=132, 66KB).
// A read straight from global (L2-hot; each CTA reads only its own rows,
// 16-lane-broadcast LDG.128). Thread tile 4 rows x 8 cols split as
// {tn*4..+3} u {64+tn*4..+3} (R9 layout — best measured).
// Bias loaded in epilogue to keep mainloop registers <= 64.
// ---------------------------------------------------------------------------
#define LDW 132
#define BMG 128
#define GEMM_T 512
#define SMEM_BYTES (128 * LDW * 4)   // 67584 B

template <bool LEAKY>
__global__ void __launch_bounds__(GEMM_T, 2)
mlp_gemm_kernel(const float* __restrict__ A,
                const float* __restrict__ W,
                const float* __restrict__ Bias,
                float* __restrict__ OUT) {
    extern __shared__ float wT[];     // [k=128][o] stride LDW

    const int tid = threadIdx.x;
    const int m0  = blockIdx.x * BMG;
    const int tm  = tid >> 4;   // 0..31 -> rows tm*4 .. tm*4+3
    const int tn  = tid & 15;   // 0..15 -> cols tn*4..+3 and 64+tn*4..+3

    // Stage W transposed: wT[k][o] = W[o*128 + k]
    for (int idx = tid; idx < 128 * 128; idx += GEMM_T) {
        int o = idx >> 7;
        int k = idx & 127;
        wT[k * LDW + o] = W[idx];
    }
    __syncthreads();

    unsigned long long acc[4][4];
    #pragma unroll
    for (int i = 0; i < 4; ++i)
        #pragma unroll
        for (int j = 0; j < 4; ++j) acc[i][j] = 0ull;

    const int row0 = m0 + tm * 4;
    const float* aBase = A + (size_t)row0 * DIM;
    const float* bBase = wT + tn * 4;
    bool inb[4];
    #pragma unroll
    for (int i = 0; i < 4; ++i) inb[i] = (row0 + i) < N_NODES;

    #pragma unroll 2
    for (int kc = 0; kc < 32; ++kc) {
        // A: 4 rows x 4 consecutive k each (LDG.128, L2-hot, 16-lane bcast)
        float4 a[4];
        #pragma unroll
        for (int i = 0; i < 4; ++i)
            a[i] = inb[i] ? __ldg((const float4*)(aBase + i * DIM + kc * 4))
                          : make_float4(0.f, 0.f, 0.f, 0.f);

        #pragma unroll
        for (int q = 0; q < 4; ++q) {
            int k = kc * 4 + q;
            ulonglong2 bA = *(const ulonglong2*)(bBase + k * LDW);       // cols tn*4..+3
            ulonglong2 bB = *(const ulonglong2*)(bBase + k * LDW + 64);  // cols 64+tn*4..+3
            const float* af0 = (const float*)&a[0];
            const float* af1 = (const float*)&a[1];
            const float* af2 = (const float*)&a[2];
            const float* af3 = (const float*)&a[3];
            unsigned long long a0 = pack2(af0[q]);
            unsigned long long a1 = pack2(af1[q]);
            unsigned long long a2 = pack2(af2[q]);
            unsigned long long a3 = pack2(af3[q]);
            fma2(acc[0][0], a0, bA.x); fma2(acc[0][1], a0, bA.y);
            fma2(acc[0][2], a0, bB.x); fma2(acc[0][3], a0, bB.y);
            fma2(acc[1][0], a1, bA.x); fma2(acc[1][1], a1, bA.y);
            fma2(acc[1][2], a1, bB.x); fma2(acc[1][3], a1, bB.y);
            fma2(acc[2][0], a2, bA.x); fma2(acc[2][1], a2, bA.y);
            fma2(acc[2][2], a2, bB.x); fma2(acc[2][3], a2, bB.y);
            fma2(acc[3][0], a3, bA.x); fma2(acc[3][1], a3, bA.y);
            fma2(acc[3][2], a3, bB.x); fma2(acc[3][3], a3, bB.y);
        }
    }

    // Epilogue: bias (+LeakyReLU) and store (two float4 per row)
    float bias[8];
    #pragma unroll
    for (int j = 0; j < 4; ++j) {
        bias[j]     = __ldg(&Bias[tn * 4 + j]);
        bias[4 + j] = __ldg(&Bias[64 + tn * 4 + j]);
    }
    #pragma unroll
    for (int i = 0; i < 4; ++i) {
        int m = row0 + i;
        if (m < N_NODES) {
            float o[8];
            unpack2(acc[i][0], o[0], o[1]);
            unpack2(acc[i][1], o[2], o[3]);
            unpack2(acc[i][2], o[4], o[5]);
            unpack2(acc[i][3], o[6], o[7]);
            #pragma unroll
            for (int j = 0; j < 8; ++j) {
                float v = o[j] + bias[j];
                if (LEAKY) v = (v >= 0.0f) ? v : 0.01f * v;
                o[j] = v;
            }
            *(float4*)(OUT + (size_t)m * DIM + tn * 4)      = make_float4(o[0], o[1], o[2], o[3]);
            *(float4*)(OUT + (size_t)m * DIM + 64 + tn * 4) = make_float4(o[4], o[5], o[6], o[7]);
        }
    }
}

// ---------------------------------------------------------------------------
// Launcher — order: histscan(0), fill(1), agg(2), gemm1(3) <- ncu, gemm2(4)
// ---------------------------------------------------------------------------
extern "C" void kernel_launch(void* const* d_in, const int* in_sizes, int n_in,
                              void* d_out, int out_size) {
    const float* x   = (const float*)d_in[0];
    const int*   ei  = (const int*)d_in[1];
    const float* ew  = (const float*)d_in[2];
    const float* w1  = (const float*)d_in[3];
    const float* b1  = (const float*)d_in[4];
    const float* w2  = (const float*)d_in[5];
    const float* b2  = (const float*)d_in[6];
    const float* eps = (const float*)d_in[7];
    float*       out = (float*)d_out;

    cudaFuncSetAttribute(mlp_gemm_kernel<true>,
                         cudaFuncAttributeMaxDynamicSharedMemorySize, SMEM_BYTES);
    cudaFuncSetAttribute(mlp_gemm_kernel<false>,
                         cudaFuncAttributeMaxDynamicSharedMemorySize, SMEM_BYTES);

    void *agg_p = nullptr, *h_p = nullptr;
    cudaGetSymbolAddress(&agg_p, g_agg);
    cudaGetSymbolAddress(&h_p,   g_h);
    float* agg = (float*)agg_p;
    float* h   = (float*)h_p;

    histscan_kernel<<<SCAN_B, SCAN_T>>>(ei);                         // 0
    fill_kernel<<<(E_EDGES + 255) / 256, 256>>>(ei, ew);             // 1
    agg_kernel<<<(N_NODES * 32 + 255) / 256, 256>>>(x, eps);         // 2

    {
        int blocks = (N_NODES + BMG - 1) / BMG;
        mlp_gemm_kernel<true><<<blocks, GEMM_T, SMEM_BYTES>>>(       // 3 <- ncu
            agg, w1, b1, h);
        mlp_gemm_kernel<false><<<blocks, GEMM_T, SMEM_BYTES>>>(      // 4
            h, w2, b2, out);
    }
}

// round 13
// speedup vs baseline: 1.0753x; 1.0753x over previous
#include <cuda_runtime.h>
#include <cuda_bf16.h>
#include <cstdint>

#define N_NODES 50000
#define E_EDGES 800000
#define DIM 128
#define NEG_INF_F __int_as_float(0xff800000)

#define SCAN_B 49
#define SCAN_T 1024
#define HIST_PER_T 16

// ---------------------------------------------------------------------------
// Static device scratch (zero-restored each call; graph-replay deterministic)
// ---------------------------------------------------------------------------
__device__ float g_agg[(size_t)N_NODES * DIM];   // GEMM1 input: (1+eps)x + maxagg
__device__ float g_h[(size_t)N_NODES * DIM];
__device__ int   g_is64;
__device__ int   g_cnt[N_NODES];
__device__ int   g_row[N_NODES + 1];
__device__ int   g_cur[N_NODES];
__device__ int   g_blksum[SCAN_B];
__device__ int   g_done1;
__device__ int   g_done2;
__device__ int2  g_edge[E_EDGES];

// ---------------------------------------------------------------------------
// Kernel 0: fused histogram + exclusive scan (unchanged)
// ---------------------------------------------------------------------------
__global__ void __launch_bounds__(SCAN_T, 1)
histscan_kernel(const int* __restrict__ ei32) {
    __shared__ int sh[SCAN_T];
    __shared__ int pre[SCAN_B];
    __shared__ int offset;
    __shared__ int any_nonzero;
    __shared__ int bar_ok;

    int t = threadIdx.x;
    int b = blockIdx.x;

    if (t == 0) any_nonzero = 0;
    __syncthreads();
    if (t < 256) {
        int k = t * 3000;
        if (ei32[2 * k + 1] != 0) atomicOr(&any_nonzero, 1);
    }
    __syncthreads();
    int is64 = any_nonzero ? 0 : 1;
    if (b == 0 && t == 0) g_is64 = is64;

    const long long* e64 = (const long long*)ei32;
    #pragma unroll
    for (int i = 0; i < HIST_PER_T; ++i) {
        int e = b * SCAN_T + t + i * (SCAN_B * SCAN_T);
        if (e < E_EDGES) {
            int src, dst;
            if (is64) {
                src = (int)e64[e];
                dst = (int)e64[(size_t)E_EDGES + e];
            } else {
                src = ei32[e];
                dst = ei32[(size_t)E_EDGES + e];
            }
            if ((unsigned)src < N_NODES && (unsigned)dst < N_NODES)
                atomicAdd(&g_cnt[dst], 1);
        }
    }

    __threadfence();
    __syncthreads();
    if (t == 0) {
        atomicAdd(&g_done1, 1);
        while (((volatile int*)&g_done1)[0] < SCAN_B) { }
        bar_ok = 1;
    }
    __syncthreads();
    (void)bar_ok;
    __threadfence();

    int idx = b * SCAN_T + t;
    int c = (idx < N_NODES) ? g_cnt[idx] : 0;
    if (idx < N_NODES) g_cnt[idx] = 0;
    sh[t] = c;
    __syncthreads();
    #pragma unroll
    for (int off = 1; off < SCAN_T; off <<= 1) {
        int v = (t >= off) ? sh[t - off] : 0;
        __syncthreads();
        sh[t] += v;
        __syncthreads();
    }
    int ex = sh[t] - c;
    if (t == SCAN_T - 1)
        ((volatile int*)g_blksum)[b] = sh[t] + 1;

    if (t < SCAN_B) {
        int v;
        do { v = ((volatile int*)g_blksum)[t]; } while (v == 0);
        pre[t] = v - 1;
    }
    __syncthreads();
    if (t == 0) {
        int s = 0;
        for (int i = 0; i < b; ++i) s += pre[i];
        offset = s;
    }
    __syncthreads();

    if (idx <= N_NODES) g_row[idx] = ex + offset;
    if (idx < N_NODES)  g_cur[idx] = 0;

    if (t == 0) {
        int old = atomicAdd(&g_done2, 1);
        if (old == SCAN_B - 1) {
            for (int i = 0; i < SCAN_B; ++i) g_blksum[i] = 0;
            g_done1 = 0;
            g_done2 = 0;
        }
    }
}

// ---------------------------------------------------------------------------
// Kernel 1: bucket edges by dst (unchanged)
// ---------------------------------------------------------------------------
__global__ void fill_kernel(const int* __restrict__ ei32,
                            const float* __restrict__ ew) {
    int e = blockIdx.x * blockDim.x + threadIdx.x;
    if (e >= E_EDGES) return;
    int src, dst;
    if (g_is64) {
        const long long* e64 = (const long long*)ei32;
        src = (int)e64[e];
        dst = (int)e64[(size_t)E_EDGES + e];
    } else {
        src = ei32[e];
        dst = ei32[(size_t)E_EDGES + e];
    }
    if ((unsigned)src >= N_NODES || (unsigned)dst >= N_NODES) return;
    int pos = g_row[dst] + atomicAdd(&g_cur[dst], 1);
    g_edge[pos] = make_int2(src, __float_as_int(ew[e]));
}

// ---------------------------------------------------------------------------
// Kernel 2: aggregate + fuse (unchanged)
// ---------------------------------------------------------------------------
__device__ __forceinline__ float4 max4w(float4 a, float4 v, float w) {
    a.x = fmaxf(a.x, v.x * w);
    a.y = fmaxf(a.y, v.y * w);
    a.z = fmaxf(a.z, v.z * w);
    a.w = fmaxf(a.w, v.w * w);
    return a;
}

__global__ void agg_kernel(const float* __restrict__ x,
                           const float* __restrict__ eps) {
    int warp = (blockIdx.x * blockDim.x + threadIdx.x) >> 5;
    if (warp >= N_NODES) return;
    int lane = threadIdx.x & 31;
    int beg = __ldg(&g_row[warp]);
    int end = __ldg(&g_row[warp + 1]);

    float4 acc = make_float4(NEG_INF_F, NEG_INF_F, NEG_INF_F, NEG_INF_F);
    int j = beg;
    for (; j + 8 <= end; j += 8) {
        int2 e[8];
        #pragma unroll
        for (int i = 0; i < 8; ++i) e[i] = __ldg(&g_edge[j + i]);
        float4 v[8];
        #pragma unroll
        for (int i = 0; i < 8; ++i)
            v[i] = __ldg(&((const float4*)(x + (size_t)e[i].x * DIM))[lane]);
        #pragma unroll
        for (int i = 0; i < 8; ++i)
            acc = max4w(acc, v[i], __int_as_float(e[i].y));
    }
    if (j + 4 <= end) {
        int2 e[4];
        #pragma unroll
        for (int i = 0; i < 4; ++i) e[i] = __ldg(&g_edge[j + i]);
        float4 v[4];
        #pragma unroll
        for (int i = 0; i < 4; ++i)
            v[i] = __ldg(&((const float4*)(x + (size_t)e[i].x * DIM))[lane]);
        #pragma unroll
        for (int i = 0; i < 4; ++i)
            acc = max4w(acc, v[i], __int_as_float(e[i].y));
        j += 4;
    }
    for (; j < end; ++j) {
        int2 ep = __ldg(&g_edge[j]);
        float4 v = __ldg(&((const float4*)(x + (size_t)ep.x * DIM))[lane]);
        acc = max4w(acc, v, __int_as_float(ep.y));
    }
    if (beg == end) acc = make_float4(0.f, 0.f, 0.f, 0.f);

    float s = 1.0f + __ldg(eps);
    float4 xv = __ldg(&((const float4*)(x + (size_t)warp * DIM))[lane]);
    acc.x = fmaf(s, xv.x, acc.x);
    acc.y = fmaf(s, xv.y, acc.y);
    acc.z = fmaf(s, xv.z, acc.z);
    acc.w = fmaf(s, xv.w, acc.w);
    ((float4*)(g_agg + (size_t)warp * DIM))[lane] = acc;
}

// ---------------------------------------------------------------------------
// Tensor-core GEMM via mma.sync (HMMA, base ISA — compiles for compute_103).
// OUT[m,o] = act( A[m,:] @ W[o,:]^T + Bias[o] )
// bf16x3 split: D = Ah*Wh + Al*Wh + Ah*Wl, fp32 accum in registers.
// CTA: 128x128 tile, 256 threads, warp grid 4(m) x 2(n); each warp 32x64.
// Fragments: mma.m16n8k16.row.col — A row-major [m][k] bf16 (ldmatrix x4),
// B col-major == W row-major [o][k] bf16 (plain ldmatrix x2, no trans).
// SMEM tiles padded to LDA=136 bf16/row (272B) -> ldmatrix conflict-free.
// ---------------------------------------------------------------------------
#define TC_T 256
#define LDA 136
#define TILE_B (128 * LDA * 2)      // 34816 B per bf16 tile
#define SM_AH 0
#define SM_AL (TILE_B)
#define SM_WH (2 * TILE_B)
#define SM_WL (3 * TILE_B)
#define SMEM_TC (4 * TILE_B)        // 139264 B

__device__ __forceinline__ uint32_t smem_u32(const void* p) {
    uint32_t a;
    asm("{ .reg .u64 t; cvta.to.shared.u64 t, %1; cvt.u32.u64 %0, t; }"
        : "=r"(a) : "l"(p));
    return a;
}
__device__ __forceinline__ void ldsm_x4(uint32_t* r, uint32_t addr) {
    asm volatile("ldmatrix.sync.aligned.m8n8.x4.shared.b16 {%0,%1,%2,%3}, [%4];"
                 : "=r"(r[0]), "=r"(r[1]), "=r"(r[2]), "=r"(r[3]) : "r"(addr));
}
__device__ __forceinline__ void ldsm_x2(uint32_t* r, uint32_t addr) {
    asm volatile("ldmatrix.sync.aligned.m8n8.x2.shared.b16 {%0,%1}, [%2];"
                 : "=r"(r[0]), "=r"(r[1]) : "r"(addr));
}
__device__ __forceinline__ void mma_bf16(float* d, const uint32_t* a,
                                         const uint32_t* b) {
    asm volatile(
        "mma.sync.aligned.m16n8k16.row.col.f32.bf16.bf16.f32 "
        "{%0,%1,%2,%3}, {%4,%5,%6,%7}, {%8,%9}, {%0,%1,%2,%3};"
        : "+f"(d[0]), "+f"(d[1]), "+f"(d[2]), "+f"(d[3])
        : "r"(a[0]), "r"(a[1]), "r"(a[2]), "r"(a[3]), "r"(b[0]), "r"(b[1]));
}
// split fp32 pair -> packed bf16x2 hi and lo (residual)
__device__ __forceinline__ void split2(float v0, float v1,
                                       uint32_t& hi2, uint32_t& lo2) {
    __nv_bfloat16 h0 = __float2bfloat16_rn(v0);
    __nv_bfloat16 h1 = __float2bfloat16_rn(v1);
    __nv_bfloat16 l0 = __float2bfloat16_rn(v0 - __bfloat162float(h0));
    __nv_bfloat16 l1 = __float2bfloat16_rn(v1 - __bfloat162float(h1));
    hi2 = (uint32_t)__bfloat16_as_ushort(h0) |
          ((uint32_t)__bfloat16_as_ushort(h1) << 16);
    lo2 = (uint32_t)__bfloat16_as_ushort(l0) |
          ((uint32_t)__bfloat16_as_ushort(l1) << 16);
}

template <bool LEAKY>
__global__ void __launch_bounds__(TC_T)
mlp_gemm_mma_kernel(const float* __restrict__ A,
                    const float* __restrict__ W,
                    const float* __restrict__ Bias,
                    float* __restrict__ OUT) {
    extern __shared__ char smc[];
    const uint32_t sbase = smem_u32(smc);
    const int tid  = threadIdx.x;
    const int wid  = tid >> 5;
    const int lane = tid & 31;
    const int m0   = blockIdx.x * 128;

    // ---- Stage A (hi/lo) ----
    for (int i = tid; i < 4096; i += TC_T) {
        int row = i >> 5;
        int c4  = (i & 31) * 4;
        int m   = m0 + row;
        float4 v = (m < N_NODES)
                 ? __ldg((const float4*)(A + (size_t)m * DIM + c4))
                 : make_float4(0.f, 0.f, 0.f, 0.f);
        uint32_t h0, l0, h1, l1;
        split2(v.x, v.y, h0, l0);
        split2(v.z, v.w, h1, l1);
        uint32_t boff = (uint32_t)(row * LDA + c4) * 2u;
        *(uint2*)(smc + SM_AH + boff) = make_uint2(h0, h1);
        *(uint2*)(smc + SM_AL + boff) = make_uint2(l0, l1);
    }
    // ---- Stage W (hi/lo), rows are output channels o ----
    for (int i = tid; i < 4096; i += TC_T) {
        int row = i >> 5;
        int c4  = (i & 31) * 4;
        float4 v = __ldg((const float4*)(W + (size_t)row * DIM + c4));
        uint32_t h0, l0, h1, l1;
        split2(v.x, v.y, h0, l0);
        split2(v.z, v.w, h1, l1);
        uint32_t boff = (uint32_t)(row * LDA + c4) * 2u;
        *(uint2*)(smc + SM_WH + boff) = make_uint2(h0, h1);
        *(uint2*)(smc + SM_WL + boff) = make_uint2(l0, l1);
    }
    __syncthreads();

    // ---- Warp tiling: 4 (m) x 2 (n); warp tile 32 rows x 64 cols ----
    const int wm = wid & 3;
    const int wn = wid >> 2;

    // ldmatrix lane address components
    const int a_row = (lane & 7) + (lane & 8);        // 0..15
    const int a_col = (lane >> 4) * 8;                // 0 or 8
    const int b_row = (lane & 7);
    const int b_col = ((lane >> 3) & 1) * 8;

    float d[2][8][4];
    #pragma unroll
    for (int mt = 0; mt < 2; ++mt)
        #pragma unroll
        for (int nt = 0; nt < 8; ++nt)
            #pragma unroll
            for (int q = 0; q < 4; ++q) d[mt][nt][q] = 0.0f;

    #pragma unroll 1
    for (int pass = 0; pass < 3; ++pass) {
        const uint32_t abase = sbase + ((pass == 1) ? SM_AL : SM_AH);
        const uint32_t wbase = sbase + ((pass == 2) ? SM_WL : SM_WH);
        #pragma unroll 2
        for (int ks = 0; ks < 8; ++ks) {
            const int k0 = ks * 16;
            uint32_t af[2][4];
            #pragma unroll
            for (int mt = 0; mt < 2; ++mt) {
                uint32_t addr = abase +
                    (uint32_t)((wm * 32 + mt * 16 + a_row) * LDA + k0 + a_col) * 2u;
                ldsm_x4(af[mt], addr);
            }
            uint32_t bfr[8][2];
            #pragma unroll
            for (int nt = 0; nt < 8; ++nt) {
                uint32_t addr = wbase +
                    (uint32_t)((wn * 64 + nt * 8 + b_row) * LDA + k0 + b_col) * 2u;
                ldsm_x2(bfr[nt], addr);
            }
            #pragma unroll
            for (int mt = 0; mt < 2; ++mt)
                #pragma unroll
                for (int nt = 0; nt < 8; ++nt)
                    mma_bf16(d[mt][nt], af[mt], bfr[nt]);
        }
    }

    // ---- Epilogue: bias + LeakyReLU, store from fragments ----
    const int colbase = wn * 64;
    #pragma unroll
    for (int nt = 0; nt < 8; ++nt) {
        int c = colbase + nt * 8 + (lane & 3) * 2;
        float2 bs = __ldg((const float2*)&Bias[c]);
        #pragma unroll
        for (int mt = 0; mt < 2; ++mt) {
            int r0 = m0 + wm * 32 + mt * 16 + (lane >> 2);
            const float* dd = d[mt][nt];
            if (r0 < N_NODES) {
                float v0 = dd[0] + bs.x;
                float v1 = dd[1] + bs.y;
                if (LEAKY) {
                    v0 = (v0 >= 0.0f) ? v0 : 0.01f * v0;
                    v1 = (v1 >= 0.0f) ? v1 : 0.01f * v1;
                }
                *(float2*)(OUT + (size_t)r0 * DIM + c) = make_float2(v0, v1);
            }
            int r1 = r0 + 8;
            if (r1 < N_NODES) {
                float v2 = dd[2] + bs.x;
                float v3 = dd[3] + bs.y;
                if (LEAKY) {
                    v2 = (v2 >= 0.0f) ? v2 : 0.01f * v2;
                    v3 = (v3 >= 0.0f) ? v3 : 0.01f * v3;
                }
                *(float2*)(OUT + (size_t)r1 * DIM + c) = make_float2(v2, v3);
            }
        }
    }
}

// ---------------------------------------------------------------------------
// Launcher — order: histscan(0), fill(1), agg(2), gemm1(3) <- ncu, gemm2(4)
// ---------------------------------------------------------------------------
extern "C" void kernel_launch(void* const* d_in, const int* in_sizes, int n_in,
                              void* d_out, int out_size) {
    const float* x   = (const float*)d_in[0];
    const int*   ei  = (const int*)d_in[1];
    const float* ew  = (const float*)d_in[2];
    const float* w1  = (const float*)d_in[3];
    const float* b1  = (const float*)d_in[4];
    const float* w2  = (const float*)d_in[5];
    const float* b2  = (const float*)d_in[6];
    const float* eps = (const float*)d_in[7];
    float*       out = (float*)d_out;

    cudaFuncSetAttribute(mlp_gemm_mma_kernel<true>,
                         cudaFuncAttributeMaxDynamicSharedMemorySize, SMEM_TC);
    cudaFuncSetAttribute(mlp_gemm_mma_kernel<false>,
                         cudaFuncAttributeMaxDynamicSharedMemorySize, SMEM_TC);

    void *agg_p = nullptr, *h_p = nullptr;
    cudaGetSymbolAddress(&agg_p, g_agg);
    cudaGetSymbolAddress(&h_p,   g_h);
    float* agg = (float*)agg_p;
    float* h   = (float*)h_p;

    histscan_kernel<<<SCAN_B, SCAN_T>>>(ei);                         // 0
    fill_kernel<<<(E_EDGES + 255) / 256, 256>>>(ei, ew);             // 1
    agg_kernel<<<(N_NODES * 32 + 255) / 256, 256>>>(x, eps);         // 2

    {
        int blocks = (N_NODES + 127) / 128;
        mlp_gemm_mma_kernel<true><<<blocks, TC_T, SMEM_TC>>>(        // 3 <- ncu
            agg, w1, b1, h);
        mlp_gemm_mma_kernel<false><<<blocks, TC_T, SMEM_TC>>>(       // 4
            h, w2, b2, out);
    }
}

// round 14
// speedup vs baseline: 1.2865x; 1.1965x over previous
#include <cuda_runtime.h>
#include <cuda_bf16.h>
#include <cstdint>

#define N_NODES 50000
#define E_EDGES 800000
#define DIM 128
#define NEG_INF_F __int_as_float(0xff800000)

#define SCAN_B 49
#define SCAN_T 1024
#define HIST_PER_T 16

// ---------------------------------------------------------------------------
// Static device scratch (zero-restored each call; graph-replay deterministic)
// ---------------------------------------------------------------------------
__device__ float g_agg[(size_t)N_NODES * DIM];   // GEMM1 input: (1+eps)x + maxagg
__device__ float g_h[(size_t)N_NODES * DIM];
__device__ int   g_is64;
__device__ int   g_cnt[N_NODES];
__device__ int   g_row[N_NODES + 1];
__device__ int   g_cur[N_NODES];
__device__ int   g_blksum[SCAN_B];
__device__ int   g_done1;
__device__ int   g_done2;
__device__ int2  g_edge[E_EDGES];

// ---------------------------------------------------------------------------
// Kernel 0: fused histogram + exclusive scan (unchanged)
// ---------------------------------------------------------------------------
__global__ void __launch_bounds__(SCAN_T, 1)
histscan_kernel(const int* __restrict__ ei32) {
    __shared__ int sh[SCAN_T];
    __shared__ int pre[SCAN_B];
    __shared__ int offset;
    __shared__ int any_nonzero;
    __shared__ int bar_ok;

    int t = threadIdx.x;
    int b = blockIdx.x;

    if (t == 0) any_nonzero = 0;
    __syncthreads();
    if (t < 256) {
        int k = t * 3000;
        if (ei32[2 * k + 1] != 0) atomicOr(&any_nonzero, 1);
    }
    __syncthreads();
    int is64 = any_nonzero ? 0 : 1;
    if (b == 0 && t == 0) g_is64 = is64;

    const long long* e64 = (const long long*)ei32;
    #pragma unroll
    for (int i = 0; i < HIST_PER_T; ++i) {
        int e = b * SCAN_T + t + i * (SCAN_B * SCAN_T);
        if (e < E_EDGES) {
            int src, dst;
            if (is64) {
                src = (int)e64[e];
                dst = (int)e64[(size_t)E_EDGES + e];
            } else {
                src = ei32[e];
                dst = ei32[(size_t)E_EDGES + e];
            }
            if ((unsigned)src < N_NODES && (unsigned)dst < N_NODES)
                atomicAdd(&g_cnt[dst], 1);
        }
    }

    __threadfence();
    __syncthreads();
    if (t == 0) {
        atomicAdd(&g_done1, 1);
        while (((volatile int*)&g_done1)[0] < SCAN_B) { }
        bar_ok = 1;
    }
    __syncthreads();
    (void)bar_ok;
    __threadfence();

    int idx = b * SCAN_T + t;
    int c = (idx < N_NODES) ? g_cnt[idx] : 0;
    if (idx < N_NODES) g_cnt[idx] = 0;
    sh[t] = c;
    __syncthreads();
    #pragma unroll
    for (int off = 1; off < SCAN_T; off <<= 1) {
        int v = (t >= off) ? sh[t - off] : 0;
        __syncthreads();
        sh[t] += v;
        __syncthreads();
    }
    int ex = sh[t] - c;
    if (t == SCAN_T - 1)
        ((volatile int*)g_blksum)[b] = sh[t] + 1;

    if (t < SCAN_B) {
        int v;
        do { v = ((volatile int*)g_blksum)[t]; } while (v == 0);
        pre[t] = v - 1;
    }
    __syncthreads();
    if (t == 0) {
        int s = 0;
        for (int i = 0; i < b; ++i) s += pre[i];
        offset = s;
    }
    __syncthreads();

    if (idx <= N_NODES) g_row[idx] = ex + offset;
    if (idx < N_NODES)  g_cur[idx] = 0;

    if (t == 0) {
        int old = atomicAdd(&g_done2, 1);
        if (old == SCAN_B - 1) {
            for (int i = 0; i < SCAN_B; ++i) g_blksum[i] = 0;
            g_done1 = 0;
            g_done2 = 0;
        }
    }
}

// ---------------------------------------------------------------------------
// Kernel 1: bucket edges by dst (unchanged)
// ---------------------------------------------------------------------------
__global__ void fill_kernel(const int* __restrict__ ei32,
                            const float* __restrict__ ew) {
    int e = blockIdx.x * blockDim.x + threadIdx.x;
    if (e >= E_EDGES) return;
    int src, dst;
    if (g_is64) {
        const long long* e64 = (const long long*)ei32;
        src = (int)e64[e];
        dst = (int)e64[(size_t)E_EDGES + e];
    } else {
        src = ei32[e];
        dst = ei32[(size_t)E_EDGES + e];
    }
    if ((unsigned)src >= N_NODES || (unsigned)dst >= N_NODES) return;
    int pos = g_row[dst] + atomicAdd(&g_cur[dst], 1);
    g_edge[pos] = make_int2(src, __float_as_int(ew[e]));
}

// ---------------------------------------------------------------------------
// Kernel 2: aggregate + fuse (unchanged)
// ---------------------------------------------------------------------------
__device__ __forceinline__ float4 max4w(float4 a, float4 v, float w) {
    a.x = fmaxf(a.x, v.x * w);
    a.y = fmaxf(a.y, v.y * w);
    a.z = fmaxf(a.z, v.z * w);
    a.w = fmaxf(a.w, v.w * w);
    return a;
}

__global__ void agg_kernel(const float* __restrict__ x,
                           const float* __restrict__ eps) {
    int warp = (blockIdx.x * blockDim.x + threadIdx.x) >> 5;
    if (warp >= N_NODES) return;
    int lane = threadIdx.x & 31;
    int beg = __ldg(&g_row[warp]);
    int end = __ldg(&g_row[warp + 1]);

    float4 acc = make_float4(NEG_INF_F, NEG_INF_F, NEG_INF_F, NEG_INF_F);
    int j = beg;
    for (; j + 8 <= end; j += 8) {
        int2 e[8];
        #pragma unroll
        for (int i = 0; i < 8; ++i) e[i] = __ldg(&g_edge[j + i]);
        float4 v[8];
        #pragma unroll
        for (int i = 0; i < 8; ++i)
            v[i] = __ldg(&((const float4*)(x + (size_t)e[i].x * DIM))[lane]);
        #pragma unroll
        for (int i = 0; i < 8; ++i)
            acc = max4w(acc, v[i], __int_as_float(e[i].y));
    }
    if (j + 4 <= end) {
        int2 e[4];
        #pragma unroll
        for (int i = 0; i < 4; ++i) e[i] = __ldg(&g_edge[j + i]);
        float4 v[4];
        #pragma unroll
        for (int i = 0; i < 4; ++i)
            v[i] = __ldg(&((const float4*)(x + (size_t)e[i].x * DIM))[lane]);
        #pragma unroll
        for (int i = 0; i < 4; ++i)
            acc = max4w(acc, v[i], __int_as_float(e[i].y));
        j += 4;
    }
    for (; j < end; ++j) {
        int2 ep = __ldg(&g_edge[j]);
        float4 v = __ldg(&((const float4*)(x + (size_t)ep.x * DIM))[lane]);
        acc = max4w(acc, v, __int_as_float(ep.y));
    }
    if (beg == end) acc = make_float4(0.f, 0.f, 0.f, 0.f);

    float s = 1.0f + __ldg(eps);
    float4 xv = __ldg(&((const float4*)(x + (size_t)warp * DIM))[lane]);
    acc.x = fmaf(s, xv.x, acc.x);
    acc.y = fmaf(s, xv.y, acc.y);
    acc.z = fmaf(s, xv.z, acc.z);
    acc.w = fmaf(s, xv.w, acc.w);
    ((float4*)(g_agg + (size_t)warp * DIM))[lane] = acc;
}

// ---------------------------------------------------------------------------
// Tensor-core GEMM via mma.sync (HMMA). OUT = act(A @ W^T + Bias).
// bf16x3 split: D = Ah*Wh + Al*Wh + Ah*Wl, fp32 accum in registers.
// CTA: 128x128 tile, 512 threads, warp grid 4(m) x 4(n); warp tile 32x32.
// A row-major [m][k] (ldmatrix x4); B col-major == W row-major [o][k]
// (plain ldmatrix x2). LDA=136 padding -> conflict-free ldmatrix.
// ---------------------------------------------------------------------------
#define TC_T 512
#define LDA 136
#define TILE_B (128 * LDA * 2)      // 34816 B per bf16 tile
#define SM_AH 0
#define SM_AL (TILE_B)
#define SM_WH (2 * TILE_B)
#define SM_WL (3 * TILE_B)
#define SMEM_TC (4 * TILE_B)        // 139264 B

__device__ __forceinline__ uint32_t smem_u32(const void* p) {
    uint32_t a;
    asm("{ .reg .u64 t; cvta.to.shared.u64 t, %1; cvt.u32.u64 %0, t; }"
        : "=r"(a) : "l"(p));
    return a;
}
__device__ __forceinline__ void ldsm_x4(uint32_t* r, uint32_t addr) {
    asm volatile("ldmatrix.sync.aligned.m8n8.x4.shared.b16 {%0,%1,%2,%3}, [%4];"
                 : "=r"(r[0]), "=r"(r[1]), "=r"(r[2]), "=r"(r[3]) : "r"(addr));
}
__device__ __forceinline__ void ldsm_x2(uint32_t* r, uint32_t addr) {
    asm volatile("ldmatrix.sync.aligned.m8n8.x2.shared.b16 {%0,%1}, [%2];"
                 : "=r"(r[0]), "=r"(r[1]) : "r"(addr));
}
__device__ __forceinline__ void mma_bf16(float* d, const uint32_t* a,
                                         const uint32_t* b) {
    asm volatile(
        "mma.sync.aligned.m16n8k16.row.col.f32.bf16.bf16.f32 "
        "{%0,%1,%2,%3}, {%4,%5,%6,%7}, {%8,%9}, {%0,%1,%2,%3};"
        : "+f"(d[0]), "+f"(d[1]), "+f"(d[2]), "+f"(d[3])
        : "r"(a[0]), "r"(a[1]), "r"(a[2]), "r"(a[3]), "r"(b[0]), "r"(b[1]));
}
__device__ __forceinline__ void split2(float v0, float v1,
                                       uint32_t& hi2, uint32_t& lo2) {
    __nv_bfloat16 h0 = __float2bfloat16_rn(v0);
    __nv_bfloat16 h1 = __float2bfloat16_rn(v1);
    __nv_bfloat16 l0 = __float2bfloat16_rn(v0 - __bfloat162float(h0));
    __nv_bfloat16 l1 = __float2bfloat16_rn(v1 - __bfloat162float(h1));
    hi2 = (uint32_t)__bfloat16_as_ushort(h0) |
          ((uint32_t)__bfloat16_as_ushort(h1) << 16);
    lo2 = (uint32_t)__bfloat16_as_ushort(l0) |
          ((uint32_t)__bfloat16_as_ushort(l1) << 16);
}

template <bool LEAKY>
__global__ void __launch_bounds__(TC_T)
mlp_gemm_mma_kernel(const float* __restrict__ A,
                    const float* __restrict__ W,
                    const float* __restrict__ Bias,
                    float* __restrict__ OUT) {
    extern __shared__ char smc[];
    const uint32_t sbase = smem_u32(smc);
    const int tid  = threadIdx.x;
    const int wid  = tid >> 5;
    const int lane = tid & 31;
    const int m0   = blockIdx.x * 128;

    // ---- Stage A (hi/lo): 4096 float4 over 512 threads = 8 per thread ----
    for (int i = tid; i < 4096; i += TC_T) {
        int row = i >> 5;
        int c4  = (i & 31) * 4;
        int m   = m0 + row;
        float4 v = (m < N_NODES)
                 ? __ldg((const float4*)(A + (size_t)m * DIM + c4))
                 : make_float4(0.f, 0.f, 0.f, 0.f);
        uint32_t h0, l0, h1, l1;
        split2(v.x, v.y, h0, l0);
        split2(v.z, v.w, h1, l1);
        uint32_t boff = (uint32_t)(row * LDA + c4) * 2u;
        *(uint2*)(smc + SM_AH + boff) = make_uint2(h0, h1);
        *(uint2*)(smc + SM_AL + boff) = make_uint2(l0, l1);
    }
    // ---- Stage W (hi/lo) ----
    for (int i = tid; i < 4096; i += TC_T) {
        int row = i >> 5;
        int c4  = (i & 31) * 4;
        float4 v = __ldg((const float4*)(W + (size_t)row * DIM + c4));
        uint32_t h0, l0, h1, l1;
        split2(v.x, v.y, h0, l0);
        split2(v.z, v.w, h1, l1);
        uint32_t boff = (uint32_t)(row * LDA + c4) * 2u;
        *(uint2*)(smc + SM_WH + boff) = make_uint2(h0, h1);
        *(uint2*)(smc + SM_WL + boff) = make_uint2(l0, l1);
    }
    __syncthreads();

    // ---- Warp tiling: 4(m) x 4(n); warp tile 32 rows x 32 cols ----
    const int wm = wid & 3;
    const int wn = wid >> 2;

    const int a_row = (lane & 7) + (lane & 8);        // 0..15
    const int a_col = (lane >> 4) * 8;                // 0 or 8
    const int b_row = (lane & 7);
    const int b_col = ((lane >> 3) & 1) * 8;

    float d[2][4][4];
    #pragma unroll
    for (int mt = 0; mt < 2; ++mt)
        #pragma unroll
        for (int nt = 0; nt < 4; ++nt)
            #pragma unroll
            for (int q = 0; q < 4; ++q) d[mt][nt][q] = 0.0f;

    #pragma unroll 1
    for (int pass = 0; pass < 3; ++pass) {
        const uint32_t abase = sbase + ((pass == 1) ? SM_AL : SM_AH);
        const uint32_t wbase = sbase + ((pass == 2) ? SM_WL : SM_WH);
        #pragma unroll 2
        for (int ks = 0; ks < 8; ++ks) {
            const int k0 = ks * 16;
            uint32_t af[2][4];
            #pragma unroll
            for (int mt = 0; mt < 2; ++mt) {
                uint32_t addr = abase +
                    (uint32_t)((wm * 32 + mt * 16 + a_row) * LDA + k0 + a_col) * 2u;
                ldsm_x4(af[mt], addr);
            }
            uint32_t bfr[4][2];
            #pragma unroll
            for (int nt = 0; nt < 4; ++nt) {
                uint32_t addr = wbase +
                    (uint32_t)((wn * 32 + nt * 8 + b_row) * LDA + k0 + b_col) * 2u;
                ldsm_x2(bfr[nt], addr);
            }
            #pragma unroll
            for (int mt = 0; mt < 2; ++mt)
                #pragma unroll
                for (int nt = 0; nt < 4; ++nt)
                    mma_bf16(d[mt][nt], af[mt], bfr[nt]);
        }
    }

    // ---- Epilogue: bias + LeakyReLU, store from fragments ----
    const int colbase = wn * 32;
    #pragma unroll
    for (int nt = 0; nt < 4; ++nt) {
        int c = colbase + nt * 8 + (lane & 3) * 2;
        float2 bs = __ldg((const float2*)&Bias[c]);
        #pragma unroll
        for (int mt = 0; mt < 2; ++mt) {
            int r0 = m0 + wm * 32 + mt * 16 + (lane >> 2);
            const float* dd = d[mt][nt];
            if (r0 < N_NODES) {
                float v0 = dd[0] + bs.x;
                float v1 = dd[1] + bs.y;
                if (LEAKY) {
                    v0 = (v0 >= 0.0f) ? v0 : 0.01f * v0;
                    v1 = (v1 >= 0.0f) ? v1 : 0.01f * v1;
                }
                *(float2*)(OUT + (size_t)r0 * DIM + c) = make_float2(v0, v1);
            }
            int r1 = r0 + 8;
            if (r1 < N_NODES) {
                float v2 = dd[2] + bs.x;
                float v3 = dd[3] + bs.y;
                if (LEAKY) {
                    v2 = (v2 >= 0.0f) ? v2 : 0.01f * v2;
                    v3 = (v3 >= 0.0f) ? v3 : 0.01f * v3;
                }
                *(float2*)(OUT + (size_t)r1 * DIM + c) = make_float2(v2, v3);
            }
        }
    }
}

// ---------------------------------------------------------------------------
// Launcher — order: histscan(0), fill(1), agg(2), gemm1(3) <- ncu, gemm2(4)
// ---------------------------------------------------------------------------
extern "C" void kernel_launch(void* const* d_in, const int* in_sizes, int n_in,
                              void* d_out, int out_size) {
    const float* x   = (const float*)d_in[0];
    const int*   ei  = (const int*)d_in[1];
    const float* ew  = (const float*)d_in[2];
    const float* w1  = (const float*)d_in[3];
    const float* b1  = (const float*)d_in[4];
    const float* w2  = (const float*)d_in[5];
    const float* b2  = (const float*)d_in[6];
    const float* eps = (const float*)d_in[7];
    float*       out = (float*)d_out;

    cudaFuncSetAttribute(mlp_gemm_mma_kernel<true>,
                         cudaFuncAttributeMaxDynamicSharedMemorySize, SMEM_TC);
    cudaFuncSetAttribute(mlp_gemm_mma_kernel<false>,
                         cudaFuncAttributeMaxDynamicSharedMemorySize, SMEM_TC);

    void *agg_p = nullptr, *h_p = nullptr;
    cudaGetSymbolAddress(&agg_p, g_agg);
    cudaGetSymbolAddress(&h_p,   g_h);
    float* agg = (float*)agg_p;
    float* h   = (float*)h_p;

    histscan_kernel<<<SCAN_B, SCAN_T>>>(ei);                         // 0
    fill_kernel<<<(E_EDGES + 255) / 256, 256>>>(ei, ew);             // 1
    agg_kernel<<<(N_NODES * 32 + 255) / 256, 256>>>(x, eps);         // 2

    {
        int blocks = (N_NODES + 127) / 128;
        mlp_gemm_mma_kernel<true><<<blocks, TC_T, SMEM_TC>>>(        // 3 <- ncu
            agg, w1, b1, h);
        mlp_gemm_mma_kernel<false><<<blocks, TC_T, SMEM_TC>>>(       // 4
            h, w2, b2, out);
    }
}